// round 2
// baseline (speedup 1.0000x reference)
#include <cuda_runtime.h>
#include <cstdint>

// out[b, idx] = prod_w ( bit_{19-w}(idx) ? sin(h[b,w]) : cos(h[b,w]) ),
// h = (x + params) * 0.5. Wire w <-> idx bit (19-w).
// Each block: batch b, 16 contiguous hi values -> one contiguous 64 KB chunk.
// Compute into SMEM, then a single TMA bulk store (cp.async.bulk) to GMEM,
// bypassing the per-thread L1tex store path.

#define N_WIRES 20
#define BATCH 64
#define HI_PER_BLOCK 16
#define THREADS 256
#define CHUNK_BYTES (HI_PER_BLOCK * 1024 * 4)   // 65536

__global__ __launch_bounds__(THREADS)
void qansatz_kernel(const float* __restrict__ x,
                    const float* __restrict__ params,
                    float* __restrict__ out)
{
    __shared__ float sc[N_WIRES];
    __shared__ float ss[N_WIRES];
    __shared__ float t_lo[1024];
    __shared__ float p_hi[HI_PER_BLOCK];
    extern __shared__ float sbuf[];              // 16 * 1024 floats = 64 KB

    const int b       = blockIdx.y;
    const int hi_base = blockIdx.x * HI_PER_BLOCK;
    const int tid     = threadIdx.x;

    // 1) cos/sin for this batch's 20 wires
    if (tid < N_WIRES) {
        float h = (x[b * N_WIRES + tid] + params[tid]) * 0.5f;
        float c, s;
        sincosf(h, &s, &c);
        sc[tid] = c;
        ss[tid] = s;
    }
    __syncthreads();

    // 2) low-bits table: product over wires 19..10 (idx bits 0..9)
    #pragma unroll
    for (int r = 0; r < 4; r++) {
        int lo = tid + r * 256;
        float p = 1.0f;
        #pragma unroll
        for (int q = 0; q < 10; q++)
            p *= ((lo >> q) & 1) ? ss[19 - q] : sc[19 - q];
        t_lo[lo] = p;
    }

    // 3) hi products: product over wires 9..0 (idx bits 10..19)
    if (tid < HI_PER_BLOCK) {
        int h = hi_base + tid;
        float p = 1.0f;
        #pragma unroll
        for (int q = 0; q < 10; q++)
            p *= ((h >> q) & 1) ? ss[9 - q] : sc[9 - q];
        p_hi[tid] = p;
    }
    __syncthreads();

    // 4) compute chunk into SMEM (STS.128, no L1tex store traffic)
    const float4* t4 = reinterpret_cast<const float4*>(t_lo);
    float4 lo4 = t4[tid];
    float4* s4 = reinterpret_cast<float4*>(sbuf);
    #pragma unroll
    for (int i = 0; i < HI_PER_BLOCK; i++) {
        float ph = p_hi[i];
        float4 v;
        v.x = ph * lo4.x;
        v.y = ph * lo4.y;
        v.z = ph * lo4.z;
        v.w = ph * lo4.w;
        s4[i * 256 + tid] = v;
    }
    __syncthreads();

    // 5) one TMA bulk store for the whole contiguous 64 KB chunk
    if (tid == 0) {
        size_t base = ((size_t)b << 20) + ((size_t)hi_base << 10);
        float* gptr = out + base;
        uint32_t saddr;
        asm volatile("{ .reg .u64 t; cvta.to.shared.u64 t, %1; cvt.u32.u64 %0, t; }"
                     : "=r"(saddr) : "l"(sbuf));
        asm volatile("fence.proxy.async.shared::cta;" ::: "memory");
        asm volatile("cp.async.bulk.global.shared::cta.bulk_group [%0], [%1], %2;"
                     :: "l"(gptr), "r"(saddr), "r"((uint32_t)CHUNK_BYTES) : "memory");
        asm volatile("cp.async.bulk.commit_group;" ::: "memory");
        asm volatile("cp.async.bulk.wait_group.read 0;" ::: "memory");
    }
}

extern "C" void kernel_launch(void* const* d_in, const int* in_sizes, int n_in,
                              void* d_out, int out_size)
{
    const float* x      = (const float*)d_in[0];   // (64, 20)
    const float* params = (const float*)d_in[1];   // (20,)
    float* out          = (float*)d_out;           // (64, 2^20)

    static int attr_set = 0;
    if (!attr_set) {
        cudaFuncSetAttribute(qansatz_kernel,
                             cudaFuncAttributeMaxDynamicSharedMemorySize,
                             CHUNK_BYTES);
        attr_set = 1;
    }

    dim3 grid(1024 / HI_PER_BLOCK, BATCH);         // (64, 64)
    qansatz_kernel<<<grid, THREADS, CHUNK_BYTES>>>(x, params, out);
}